// round 1
// baseline (speedup 1.0000x reference)
#include <cuda_runtime.h>
#include <math.h>

#define BB 4
#define HH 8
#define TT 2048
#define DD 64
#define EE 512
#define WIN 128
#define TOPKK 96
#define QT 64
#define KROWS 192
#define KPAD 68
#define PPAD 132

// Scratch (device globals; no allocation allowed)
__device__ float g_q[(size_t)BB * HH * TT * DD];
__device__ float g_k[(size_t)BB * HH * TT * DD];
__device__ float g_v[(size_t)BB * HH * TT * DD];
__device__ float g_attn[(size_t)BB * TT * EE];

__device__ __forceinline__ unsigned f2ord(float f) {
    unsigned u = __float_as_uint(f);
    return (u & 0x80000000u) ? ~u : (u | 0x80000000u);
}

// ---------------------------------------------------------------------------
// GEMM: Y = X @ W^T + bias.  X:[M,512] row-major, W:[512,512] row-major.
// 64x64 block tile, 256 threads, 4x4 per-thread tile, BK=16.
// HEADSPLIT: write out[((b*H+h)*T + t)*64 + d]  (n-block == one head since BN=D=64)
// ---------------------------------------------------------------------------
template <bool HEADSPLIT>
__global__ __launch_bounds__(256) void gemm64(const float* __restrict__ X,
                                              const float* __restrict__ W,
                                              const float* __restrict__ bias,
                                              float* __restrict__ Y) {
    __shared__ float Xs[16][KPAD];
    __shared__ float Ws[16][KPAD];
    const int m0 = blockIdx.x * 64;
    const int n0 = blockIdx.y * 64;
    const int tid = threadIdx.x;
    const int tx = tid & 15, ty = tid >> 4;
    const int lr = tid >> 2, lc = tid & 3;

    float acc[4][4];
#pragma unroll
    for (int i = 0; i < 4; i++)
#pragma unroll
        for (int j = 0; j < 4; j++) acc[i][j] = 0.f;

    const float* Xp = X + (size_t)(m0 + lr) * EE + lc * 4;
    const float* Wp = W + (size_t)(n0 + lr) * EE + lc * 4;

    for (int k0 = 0; k0 < EE; k0 += 16) {
        float4 xv = *(const float4*)(Xp + k0);
        float4 wv = *(const float4*)(Wp + k0);
        __syncthreads();
        Xs[lc * 4 + 0][lr] = xv.x;
        Xs[lc * 4 + 1][lr] = xv.y;
        Xs[lc * 4 + 2][lr] = xv.z;
        Xs[lc * 4 + 3][lr] = xv.w;
        Ws[lc * 4 + 0][lr] = wv.x;
        Ws[lc * 4 + 1][lr] = wv.y;
        Ws[lc * 4 + 2][lr] = wv.z;
        Ws[lc * 4 + 3][lr] = wv.w;
        __syncthreads();
#pragma unroll
        for (int kk = 0; kk < 16; kk++) {
            float4 a = *(const float4*)&Xs[kk][ty * 4];
            float4 b = *(const float4*)&Ws[kk][tx * 4];
            acc[0][0] = fmaf(a.x, b.x, acc[0][0]);
            acc[0][1] = fmaf(a.x, b.y, acc[0][1]);
            acc[0][2] = fmaf(a.x, b.z, acc[0][2]);
            acc[0][3] = fmaf(a.x, b.w, acc[0][3]);
            acc[1][0] = fmaf(a.y, b.x, acc[1][0]);
            acc[1][1] = fmaf(a.y, b.y, acc[1][1]);
            acc[1][2] = fmaf(a.y, b.z, acc[1][2]);
            acc[1][3] = fmaf(a.y, b.w, acc[1][3]);
            acc[2][0] = fmaf(a.z, b.x, acc[2][0]);
            acc[2][1] = fmaf(a.z, b.y, acc[2][1]);
            acc[2][2] = fmaf(a.z, b.z, acc[2][2]);
            acc[2][3] = fmaf(a.z, b.w, acc[2][3]);
            acc[3][0] = fmaf(a.w, b.x, acc[3][0]);
            acc[3][1] = fmaf(a.w, b.y, acc[3][1]);
            acc[3][2] = fmaf(a.w, b.z, acc[3][2]);
            acc[3][3] = fmaf(a.w, b.w, acc[3][3]);
        }
    }

    float4 bb = *(const float4*)&bias[n0 + tx * 4];
#pragma unroll
    for (int i = 0; i < 4; i++) {
        int m = m0 + ty * 4 + i;
        float4 r = make_float4(acc[i][0] + bb.x, acc[i][1] + bb.y,
                               acc[i][2] + bb.z, acc[i][3] + bb.w);
        if (HEADSPLIT) {
            int bidx = m / TT;
            int t = m - bidx * TT;
            int h = n0 >> 6;
            *(float4*)&Y[(((size_t)bidx * HH + h) * TT + t) * DD + tx * 4] = r;
        } else {
            *(float4*)&Y[(size_t)m * EE + n0 + tx * 4] = r;
        }
    }
}

// ---------------------------------------------------------------------------
// Attention: block per (q-tile of 64, h, b). 256 threads = 8 warps.
// Window = 128 keys per query (causal), exact top-96 threshold, softmax, PV.
// ---------------------------------------------------------------------------
__global__ __launch_bounds__(256) void attn_kernel(const float* __restrict__ log_sigma) {
    extern __shared__ float sm[];
    float* sQ = sm;                         // 64  x 68
    float* sK = sQ + 64 * KPAD;             // 192 x 68
    float* sV = sK + KROWS * KPAD;          // 192 x 68
    float* sP = sV + KROWS * KPAD;          // 64  x 132

    const int q0 = blockIdx.x * QT;
    const int h = blockIdx.y;
    const int b = blockIdx.z;
    const int tid = threadIdx.x;

    const float* Qg = g_q + ((size_t)(b * HH + h) * TT) * DD;
    const float* Kg = g_k + ((size_t)(b * HH + h) * TT) * DD;
    const float* Vg = g_v + ((size_t)(b * HH + h) * TT) * DD;
    const float scale = -0.5f * expf(-2.f * log_sigma[h]);  // scores = dist * scale

    // ---- load tiles ----
    for (int i = tid; i < 64 * 16; i += 256) {
        int r = i >> 4, c = i & 15;
        *(float4*)&sQ[r * KPAD + c * 4] =
            *(const float4*)&Qg[(size_t)(q0 + r) * DD + c * 4];
    }
    const float4 z4 = make_float4(0.f, 0.f, 0.f, 0.f);
    for (int i = tid; i < KROWS * 16; i += 256) {
        int r = i >> 4, c = i & 15;
        int gk = q0 - 128 + r;
        float4 kv = z4, vv = z4;
        if (gk >= 0) {
            kv = *(const float4*)&Kg[(size_t)gk * DD + c * 4];
            vv = *(const float4*)&Vg[(size_t)gk * DD + c * 4];
        }
        *(float4*)&sK[r * KPAD + c * 4] = kv;
        *(float4*)&sV[r * KPAD + c * 4] = vv;
    }
    __syncthreads();

    // ---- scores + top-k + softmax (warp per query group; lane owns 4 keys) ----
    const int w = tid >> 5, l = tid & 31;
    const float NEGINF = __int_as_float(0xff800000);

    for (int qq = 0; qq < 8; qq++) {
        const int qi = w * 8 + qq;
        const int gq = q0 + qi;
        float dacc[4] = {0.f, 0.f, 0.f, 0.f};
        const float* qrow = &sQ[qi * KPAD];
#pragma unroll 8
        for (int c = 0; c < 16; c++) {
            float4 qv = *(const float4*)&qrow[c * 4];
#pragma unroll
            for (int t = 0; t < 4; t++) {
                const float* krow = &sK[(qi + 1 + l + 32 * t) * KPAD];
                float4 kv = *(const float4*)&krow[c * 4];
                float dx = qv.x - kv.x;
                float dy = qv.y - kv.y;
                float dz = qv.z - kv.z;
                float dw = qv.w - kv.w;
                dacc[t] = fmaf(dx, dx, dacc[t]);
                dacc[t] = fmaf(dy, dy, dacc[t]);
                dacc[t] = fmaf(dz, dz, dacc[t]);
                dacc[t] = fmaf(dw, dw, dacc[t]);
            }
        }
        float s[4];
        unsigned key[4];
        bool valid[4];
#pragma unroll
        for (int t = 0; t < 4; t++) {
            int j = l + 32 * t;
            valid[t] = (gq - 127 + j) >= 0;
            s[t] = dacc[t] * scale;
            key[t] = valid[t] ? f2ord(s[t]) : 0u;
        }

        unsigned thr = 0u;
        if (gq >= TOPKK) {  // >96 valid keys -> top-k filter active
            for (int bit = 31; bit >= 0; bit--) {
                unsigned cand = thr | (1u << bit);
                int cnt = (int)(key[0] >= cand) + (int)(key[1] >= cand) +
                          (int)(key[2] >= cand) + (int)(key[3] >= cand);
                cnt = __reduce_add_sync(0xffffffffu, cnt);
                if (cnt >= TOPKK) thr = cand;
            }
        }

        bool kept[4];
        float mv = NEGINF;
#pragma unroll
        for (int t = 0; t < 4; t++) {
            kept[t] = valid[t] && (key[t] >= thr);
            if (kept[t]) mv = fmaxf(mv, s[t]);
        }
#pragma unroll
        for (int o = 16; o > 0; o >>= 1)
            mv = fmaxf(mv, __shfl_xor_sync(0xffffffffu, mv, o));

        float e[4];
        float esum = 0.f;
#pragma unroll
        for (int t = 0; t < 4; t++) {
            e[t] = kept[t] ? __expf(s[t] - mv) : 0.f;
            esum += e[t];
        }
#pragma unroll
        for (int o = 16; o > 0; o >>= 1)
            esum += __shfl_xor_sync(0xffffffffu, esum, o);
        float inv = 1.f / esum;
#pragma unroll
        for (int t = 0; t < 4; t++) sP[qi * PPAD + l + 32 * t] = e[t] * inv;
    }
    __syncthreads();

    // ---- PV: thread (qi, dg) covers dims [8dg,8dg+8) and [32+8dg,32+8dg+8) ----
    {
        const int qi = tid >> 2;
        const int dg = tid & 3;
        const int gq = q0 + qi;
        float4 o0 = z4, o1 = z4, o2 = z4, o3 = z4;
        const float* prow = &sP[qi * PPAD];
#pragma unroll 4
        for (int j = 0; j < 128; j++) {
            float p = prow[j];
            const float4* vr = (const float4*)&sV[(qi + 1 + j) * KPAD];
            float4 a0 = vr[2 * dg + 0];
            float4 a1 = vr[2 * dg + 1];
            float4 a2 = vr[8 + 2 * dg + 0];
            float4 a3 = vr[8 + 2 * dg + 1];
            o0.x = fmaf(p, a0.x, o0.x); o0.y = fmaf(p, a0.y, o0.y);
            o0.z = fmaf(p, a0.z, o0.z); o0.w = fmaf(p, a0.w, o0.w);
            o1.x = fmaf(p, a1.x, o1.x); o1.y = fmaf(p, a1.y, o1.y);
            o1.z = fmaf(p, a1.z, o1.z); o1.w = fmaf(p, a1.w, o1.w);
            o2.x = fmaf(p, a2.x, o2.x); o2.y = fmaf(p, a2.y, o2.y);
            o2.z = fmaf(p, a2.z, o2.z); o2.w = fmaf(p, a2.w, o2.w);
            o3.x = fmaf(p, a3.x, o3.x); o3.y = fmaf(p, a3.y, o3.y);
            o3.z = fmaf(p, a3.z, o3.z); o3.w = fmaf(p, a3.w, o3.w);
        }
        size_t obase = ((size_t)b * TT + gq) * EE + h * DD;
        *(float4*)&g_attn[obase + 8 * dg + 0] = o0;
        *(float4*)&g_attn[obase + 8 * dg + 4] = o1;
        *(float4*)&g_attn[obase + 32 + 8 * dg + 0] = o2;
        *(float4*)&g_attn[obase + 32 + 8 * dg + 4] = o3;
    }
}

// ---------------------------------------------------------------------------
extern "C" void kernel_launch(void* const* d_in, const int* in_sizes, int n_in,
                              void* d_out, int out_size) {
    const float* x  = (const float*)d_in[0];
    const float* Wq = (const float*)d_in[1];
    const float* bq = (const float*)d_in[2];
    const float* Wk = (const float*)d_in[3];
    const float* bk = (const float*)d_in[4];
    const float* Wv = (const float*)d_in[5];
    const float* bv = (const float*)d_in[6];
    const float* Wo = (const float*)d_in[7];
    const float* bo = (const float*)d_in[8];
    const float* ls = (const float*)d_in[9];

    float *qp, *kp, *vp, *ap;
    cudaGetSymbolAddress((void**)&qp, g_q);
    cudaGetSymbolAddress((void**)&kp, g_k);
    cudaGetSymbolAddress((void**)&vp, g_v);
    cudaGetSymbolAddress((void**)&ap, g_attn);

    dim3 gg(BB * TT / 64, EE / 64);  // 128 x 8
    gemm64<true><<<gg, 256>>>(x, Wq, bq, qp);
    gemm64<true><<<gg, 256>>>(x, Wk, bk, kp);
    gemm64<true><<<gg, 256>>>(x, Wv, bv, vp);

    const size_t smem =
        (size_t)(64 * KPAD + 2 * KROWS * KPAD + 64 * PPAD) * sizeof(float);
    cudaFuncSetAttribute(attn_kernel, cudaFuncAttributeMaxDynamicSharedMemorySize,
                         (int)smem);
    attn_kernel<<<dim3(TT / QT, HH, BB), 256, smem>>>(ls);

    gemm64<false><<<gg, 256>>>(ap, Wo, bo, (float*)d_out);
}